// round 14
// baseline (speedup 1.0000x reference)
#include <cuda_runtime.h>

#define N_NODES   500000
#define E_EDGES   16000000
#define NVEC      (E_EDGES / 4)
#define NWARPS    (N_NODES / 32)         // 15625 warps, 32 nodes each
#define PAD       56                     // bucket slots; 112MB array fits L2. Overflow handled exactly.
#define OV_CAP    16384                  // overflow capacity (expected ~500 entries)

// ---------------------------------------------------------------------------
// Static scratch (allocation-free rule). Slots >= deg in g_srcSorted are only
// read under predicates that are false for them.
// ---------------------------------------------------------------------------
__device__ unsigned int  g_outcnt[N_NODES];
__device__ float         g_ds[N_NODES];              // out_deg^-0.5
__device__ float         g_dd[N_NODES];              // in_deg^-0.5 (TRUE in-degree)
__device__ float         g_xs[N_NODES];              // y * ds
__device__ float         g_x2[N_NODES];              // layer-2 message
__device__ unsigned int  g_end[N_NODES];             // true cursor end after scatter
__device__ unsigned int  g_cursor[N_NODES];
__device__ unsigned int  g_srcSorted[N_NODES * PAD]; // padded buckets of src ids by dst
__device__ unsigned int  g_ovCnt;                    // overflow count
__device__ unsigned int  g_ovDst[OV_CAP];            // overflow dst ids
__device__ unsigned int  g_ovSrc[OV_CAP];            // overflow src ids

// ---------------------------------------------------------------------------
// 0. init cursors + zero out-degree + zero overflow count
// ---------------------------------------------------------------------------
__global__ void init_cursor_kernel() {
    int i = blockIdx.x * blockDim.x + threadIdx.x;
    if (i < N_NODES) {
        g_cursor[i] = (unsigned int)i * PAD;
        g_outcnt[i] = 0u;
    }
    if (i == 0) g_ovCnt = 0u;
}

// ---------------------------------------------------------------------------
// 1. fused scatter: bucket placement (with exact overflow) + out-degree REDs
// ---------------------------------------------------------------------------
__device__ __forceinline__ void place_edge(unsigned int s, unsigned int d) {
    unsigned int p    = atomicAdd(&g_cursor[d], 1u);
    unsigned int base = d * PAD;
    if (p - base < PAD) {
        g_srcSorted[p] = s;
    } else {
        unsigned int q = atomicAdd(&g_ovCnt, 1u);
        if (q < OV_CAP) { g_ovDst[q] = d; g_ovSrc[q] = s; }
    }
}

__global__ void scatter_kernel(const int4* __restrict__ src4, const int4* __restrict__ dst4) {
    int i = blockIdx.x * blockDim.x + threadIdx.x;
    if (i >= NVEC) return;
    int4 s = __ldg(src4 + i);
    int4 d = __ldg(dst4 + i);
    atomicAdd(&g_outcnt[s.x], 1u);
    atomicAdd(&g_outcnt[s.y], 1u);
    atomicAdd(&g_outcnt[s.z], 1u);
    atomicAdd(&g_outcnt[s.w], 1u);
    place_edge((unsigned int)s.x, (unsigned int)d.x);
    place_edge((unsigned int)s.y, (unsigned int)d.y);
    place_edge((unsigned int)s.z, (unsigned int)d.z);
    place_edge((unsigned int)s.w, (unsigned int)d.w);
}

// ---------------------------------------------------------------------------
// 2. node init: TRUE degree norms, y sign fix, first message
// ---------------------------------------------------------------------------
__global__ void init_kernel(const float* __restrict__ y_in, float* __restrict__ y) {
    int i = blockIdx.x * blockDim.x + threadIdx.x;
    if (i >= N_NODES) return;
    unsigned int end = g_cursor[i];
    g_end[i] = end;
    float indeg = (float)(end - (unsigned int)i * PAD);   // true in-degree
    float ds = rsqrtf(fmaxf((float)g_outcnt[i], 1.0f));
    float dd = rsqrtf(fmaxf(indeg, 1.0f));
    g_ds[i] = ds;
    g_dd[i] = dd;
    float yv = y_in[i];
    yv = (yv == 0.0f) ? -1.0f : yv;
    y[i]    = yv;
    g_xs[i] = yv * ds;
}

// ---------------------------------------------------------------------------
// Sub-warp (8-lane) gather, vector index tiers (R13 shape), 2 tiers for PAD=56
// (32 + 24 slots) + exact overflow-list scan for the ~200 rare nodes.
// Round r: subwarp sw reduces node warpNode0 + r*4 + sw.
// ---------------------------------------------------------------------------
__device__ __forceinline__ float warp_gather_sw8(const float* __restrict__ vals,
                                                 int warpNode0, int lane) {
    int sw = lane >> 3;     // sub-warp id 0..3
    int sl = lane & 7;      // lane within sub-warp
    const uint4* b4 = reinterpret_cast<const uint4*>(g_srcSorted);
    float myAgg = 0.0f;
#pragma unroll 2
    for (int r = 0; r < 8; r++) {
        int node = warpNode0 + r * 4 + sw;
        unsigned int lo      = (unsigned int)node * PAD;   // 224B stride, 16B aligned
        unsigned int trueDeg = __ldg(g_end + node) - lo;
        unsigned int deg     = (trueDeg > PAD) ? (unsigned int)PAD : trueDeg;
        unsigned int v4      = (lo >> 2) + sl;
        float a = 0.0f;

        // tier 0: slots sl*4 .. sl*4+3  (0..31)
        {
            unsigned int s0 = (unsigned int)(sl * 4);
            if (s0 < deg) {
                uint4 q = __ldg(b4 + v4);
                a += __ldg(vals + q.x);
                if (s0 + 1 < deg) a += __ldg(vals + q.y);
                if (s0 + 2 < deg) a += __ldg(vals + q.z);
                if (s0 + 3 < deg) a += __ldg(vals + q.w);
            }
        }
        // tier 1: slots 32+sl*4 .. (32..55; deg<=56 keeps sl>=6 predicated off)
        {
            unsigned int s0 = 32u + (unsigned int)(sl * 4);
            if (s0 < deg) {
                uint4 q = __ldg(b4 + v4 + 8);
                a += __ldg(vals + q.x);
                if (s0 + 1 < deg) a += __ldg(vals + q.y);
                if (s0 + 2 < deg) a += __ldg(vals + q.z);
                if (s0 + 3 < deg) a += __ldg(vals + q.w);
            }
        }
        // overflow: rare (~200 nodes chip-wide), exact
        if (trueDeg > PAD) {
            unsigned int oc = g_ovCnt;
            if (oc > OV_CAP) oc = OV_CAP;
            for (unsigned int t = (unsigned int)sl; t < oc; t += 8)
                if (g_ovDst[t] == (unsigned int)node) a += __ldg(vals + g_ovSrc[t]);
        }

        a += __shfl_xor_sync(0xffffffffu, a, 1);
        a += __shfl_xor_sync(0xffffffffu, a, 2);
        a += __shfl_xor_sync(0xffffffffu, a, 4);
        float got = __shfl_sync(0xffffffffu, a, (lane & 3) << 3);
        if ((lane >> 2) == r) myAgg = got;
    }
    return myAgg;
}

// ---------------------------------------------------------------------------
// 3a. fused pass A: agg = A·xs ; fc+resid+LN+PReLU + layer-2 fc -> g_x2
// ---------------------------------------------------------------------------
__global__ __launch_bounds__(256) void passA_kernel(const float* __restrict__ y,
        const float* __restrict__ W1,  const float* __restrict__ b1,
        const float* __restrict__ Wres,
        const float* __restrict__ lng, const float* __restrict__ lnb,
        const float* __restrict__ pa,
        const float* __restrict__ W2,  const float* __restrict__ b2) {
    int gt = blockIdx.x * blockDim.x + threadIdx.x;
    int w  = gt >> 5;
    if (w >= NWARPS) return;
    int lane = gt & 31;
    int n = w * 32 + lane;

    float a = warp_gather_sw8(g_xs, w * 32, lane);

    float yv = __ldg(y + n);
    float ds = g_ds[n];
    float dd = g_dd[n];
    float alpha = __ldg(pa);
    float bias2 = __ldg(b2);

    float r[8]; float mu = 0.f;
#pragma unroll
    for (int j = 0; j < 8; j++) {
        r[j] = (a * __ldg(W1 + j) + __ldg(b1 + j)) * dd + yv * __ldg(Wres + j);
        mu += r[j];
    }
    mu *= 0.125f;
    float var = 0.f;
#pragma unroll
    for (int j = 0; j < 8; j++) { float u = r[j] - mu; var += u * u; }
    var *= 0.125f;
    float inv = rsqrtf(var + 1e-5f);
    float dot = 0.f;
#pragma unroll
    for (int j = 0; j < 8; j++) {
        float u = (r[j] - mu) * inv * __ldg(lng + j) + __ldg(lnb + j);
        u = (u >= 0.f) ? u : alpha * u;
        dot += u * __ldg(W2 + j);
    }
    g_x2[n] = ds * dot + bias2;
}

// ---------------------------------------------------------------------------
// 3b. fused pass B: agg2 = A·x2 ; y += dd*agg2 ; xs = y*ds
// ---------------------------------------------------------------------------
__global__ __launch_bounds__(256) void passB_kernel(float* __restrict__ y) {
    int gt = blockIdx.x * blockDim.x + threadIdx.x;
    int w  = gt >> 5;
    if (w >= NWARPS) return;
    int lane = gt & 31;
    int n = w * 32 + lane;

    float a = warp_gather_sw8(g_x2, w * 32, lane);

    float yv = y[n] + a * g_dd[n];
    y[n]    = yv;
    g_xs[n] = yv * g_ds[n];
}

// ---------------------------------------------------------------------------
// launch
// ---------------------------------------------------------------------------
extern "C" void kernel_launch(void* const* d_in, const int* in_sizes, int n_in,
                              void* d_out, int out_size) {
    const float* y_in = (const float*)d_in[0];
    const int*   src  = (const int*)d_in[1];
    const int*   dst  = (const int*)d_in[2];
    const float* W1   = (const float*)d_in[3];
    const float* b1   = (const float*)d_in[4];
    const float* Wres = (const float*)d_in[5];
    const float* lng  = (const float*)d_in[6];
    const float* lnb  = (const float*)d_in[7];
    const float* pa   = (const float*)d_in[8];
    const float* W2   = (const float*)d_in[9];
    const float* b2   = (const float*)d_in[10];
    float* y = (float*)d_out;

    const int TB = 256;
    int nb_n = (N_NODES + TB - 1) / TB;
    int nb_e = (NVEC + TB - 1) / TB;
    int nb_w = (NWARPS * 32 + TB - 1) / TB;

    init_cursor_kernel<<<nb_n, TB>>>();
    scatter_kernel<<<nb_e, TB>>>((const int4*)src, (const int4*)dst);
    init_kernel<<<nb_n, TB>>>(y_in, y);

    for (int l = 0; l < 4; l++) {
        passA_kernel<<<nb_w, TB>>>(y, W1, b1, Wres, lng, lnb, pa, W2, b2);
        passB_kernel<<<nb_w, TB>>>(y);
    }
}